// round 9
// baseline (speedup 1.0000x reference)
#include <cuda_runtime.h>
#include <cstdint>

// Problem constants
#define Bc    2
#define Nc    128
#define Sc    4
#define DGc   8
#define CINc  4
#define COUTc 8
#define HIDc  32

// Static smem layout (float offsets). ALL weights non-duplicated, input-major
// [c][k][o]; all weights & biases pre-scaled by 0.5 at staging (silu trick).
#define KYW1t 0        // [c][k2][o]   256
#define KGW1t 256      // [c][k8][o]   1024
#define KYB1o 1280     // [c][o]       128
#define KGB1o 1408     // 128
#define KYW2t 1536     // [c][k32][o]  4096
#define KGW2t 5632     // 4096
#define KYB2o 9728     // 128
#define KGB2o 9856     // 128
#define KYW3o 9984     // 128
#define KGW3o 10112    // 128
#define KYB3o 10240    // 4
#define KGB3o 10244    // 4
#define WOUTo 10248    // 32
#define SREDo 10280    // 64
#define SWTOT 10344

typedef unsigned long long u64;

__device__ __forceinline__ u64 pk2(float lo, float hi) {
    u64 r; asm("mov.b64 %0, {%1, %2};" : "=l"(r) : "f"(lo), "f"(hi)); return r;
}
__device__ __forceinline__ void upk2(u64 v, float& lo, float& hi) {
    asm("mov.b64 {%0, %1}, %2;" : "=f"(lo), "=f"(hi) : "l"(v));
}
__device__ __forceinline__ u64 fma2(u64 a, u64 b, u64 c) {
    u64 d; asm("fma.rn.f32x2 %0, %1, %2, %3;" : "=l"(d) : "l"(a), "l"(b), "l"(c)); return d;
}
__device__ __forceinline__ u64 add2(u64 a, u64 b) {
    u64 d; asm("add.rn.f32x2 %0, %1, %2;" : "=l"(d) : "l"(a), "l"(b)); return d;
}
__device__ __forceinline__ float ex2f(float x) {
    float r; asm("ex2.approx.f32 %0, %1;" : "=f"(r) : "f"(x)); return r;
}
__device__ __forceinline__ float tanhf_a(float x) {
    float r; asm("tanh.approx.f32 %0, %1;" : "=f"(r) : "f"(x)); return r;
}

#define LOG2E 1.4426950408889634f

// Pre-scaled silu: acc holds x/2; silu(x) = fma(acc, tanh(acc), acc).
__device__ __forceinline__ u64 silu2p(u64 acc) {
    float a, b; upk2(acc, a, b);
    u64 tp = pk2(tanhf_a(a), tanhf_a(b));
    return fma2(acc, tp, acc);
}
__device__ __forceinline__ float silu_fp(float acc) {
    return fmaf(acc, tanhf_a(acc), acc);
}

// Fused layers 2+3, 4 chunks of 8 outputs (small acc footprint).
__device__ __forceinline__ void mlp23(const u64* hpA, const u64* hpB,
                                      const float* __restrict__ w2,
                                      const float* __restrict__ b2,
                                      const float* __restrict__ w3,
                                      float b3, float& kA, float& kB)
{
    u64 tA = pk2(0.f, 0.f), tB = pk2(0.f, 0.f);

    #pragma unroll 1
    for (int ch = 0; ch < 4; ++ch) {
        u64 aA[4], aB[4];
        {
            ulonglong2 b01 = *reinterpret_cast<const ulonglong2*>(b2 + ch*8);
            ulonglong2 b23 = *reinterpret_cast<const ulonglong2*>(b2 + ch*8 + 4);
            aA[0]=b01.x; aA[1]=b01.y; aA[2]=b23.x; aA[3]=b23.y;
            aB[0]=b01.x; aB[1]=b01.y; aB[2]=b23.x; aB[3]=b23.y;
        }
        const float* wkb = w2 + ch*8;
        #pragma unroll
        for (int p = 0; p < 16; ++p) {
            float ha0, ha1, hb0, hb1;
            upk2(hpA[p], ha0, ha1);
            upk2(hpB[p], hb0, hb1);
            {   // k = 2p
                const u64 hAd = pk2(ha0, ha0);
                const u64 hBd = pk2(hb0, hb0);
                ulonglong2 w01 = *reinterpret_cast<const ulonglong2*>(wkb + (2*p)*32);
                ulonglong2 w23 = *reinterpret_cast<const ulonglong2*>(wkb + (2*p)*32 + 4);
                aA[0] = fma2(hAd, w01.x, aA[0]);
                aA[1] = fma2(hAd, w01.y, aA[1]);
                aA[2] = fma2(hAd, w23.x, aA[2]);
                aA[3] = fma2(hAd, w23.y, aA[3]);
                aB[0] = fma2(hBd, w01.x, aB[0]);
                aB[1] = fma2(hBd, w01.y, aB[1]);
                aB[2] = fma2(hBd, w23.x, aB[2]);
                aB[3] = fma2(hBd, w23.y, aB[3]);
            }
            {   // k = 2p+1
                const u64 hAd = pk2(ha1, ha1);
                const u64 hBd = pk2(hb1, hb1);
                ulonglong2 w01 = *reinterpret_cast<const ulonglong2*>(wkb + (2*p+1)*32);
                ulonglong2 w23 = *reinterpret_cast<const ulonglong2*>(wkb + (2*p+1)*32 + 4);
                aA[0] = fma2(hAd, w01.x, aA[0]);
                aA[1] = fma2(hAd, w01.y, aA[1]);
                aA[2] = fma2(hAd, w23.x, aA[2]);
                aA[3] = fma2(hAd, w23.y, aA[3]);
                aB[0] = fma2(hBd, w01.x, aB[0]);
                aB[1] = fma2(hBd, w01.y, aB[1]);
                aB[2] = fma2(hBd, w23.x, aB[2]);
                aB[3] = fma2(hBd, w23.y, aB[3]);
            }
        }
        // silu + fold into layer-3 dot (w3 pre-scaled)
        ulonglong2 p01 = *reinterpret_cast<const ulonglong2*>(w3 + ch*8);
        ulonglong2 p23 = *reinterpret_cast<const ulonglong2*>(w3 + ch*8 + 4);
        tA = fma2(silu2p(aA[0]), p01.x, tA);
        tB = fma2(silu2p(aB[0]), p01.x, tB);
        tA = fma2(silu2p(aA[1]), p01.y, tA);
        tB = fma2(silu2p(aB[1]), p01.y, tB);
        tA = fma2(silu2p(aA[2]), p23.x, tA);
        tB = fma2(silu2p(aB[2]), p23.x, tB);
        tA = fma2(silu2p(aA[3]), p23.y, tA);
        tB = fma2(silu2p(aB[3]), p23.y, tB);
    }
    float a0, a1, b0, b1v;
    upk2(tA, a0, a1);
    upk2(tB, b0, b1v);
    kA += silu_fp(a0 + a1 + b3);
    kB += silu_fp(b0 + b1v + b3);
}

__global__ __launch_bounds__(256, 2)
void ema_kernel(const float* __restrict__ g,
                const float* __restrict__ f,
                const int* __restrict__ mask,
                const float* __restrict__ kyW1, const float* __restrict__ kyb1,
                const float* __restrict__ kyW2, const float* __restrict__ kyb2,
                const float* __restrict__ kyW3, const float* __restrict__ kyb3,
                const float* __restrict__ kgW1, const float* __restrict__ kgb1,
                const float* __restrict__ kgW2, const float* __restrict__ kgb2,
                const float* __restrict__ kgW3, const float* __restrict__ kgb3,
                const float* __restrict__ wout,
                float* __restrict__ out)
{
    __shared__ __align__(16) float sw[SWTOT];

    const int tid = threadIdx.x;

    // ---- stage weights: transpose to input-major, pre-scale by 0.5 ----
    {
        for (int idx = tid; idx < 4096; idx += 256) {
            int c = idx >> 10, o = (idx >> 5) & 31, k = idx & 31;
            int d = c * 1024 + k * 32 + o;
            sw[KYW2t + d] = 0.5f * kyW2[idx];
            sw[KGW2t + d] = 0.5f * kgW2[idx];
        }
        for (int idx = tid; idx < 1024; idx += 256) {
            int c = idx >> 8, o = (idx >> 3) & 31, k = idx & 7;
            sw[KGW1t + c * 256 + k * 32 + o] = 0.5f * kgW1[idx];
        }
        if (tid < 256) {
            int idx = tid;
            int c = idx >> 6, o = (idx >> 1) & 31, k = idx & 1;
            sw[KYW1t + c * 64 + k * 32 + o] = 0.5f * kyW1[idx];
        }
        for (int idx = tid; idx < 128; idx += 256) {
            sw[KYB1o + idx] = 0.5f * kyb1[idx];
            sw[KGB1o + idx] = 0.5f * kgb1[idx];
            sw[KYB2o + idx] = 0.5f * kyb2[idx];
            sw[KGB2o + idx] = 0.5f * kgb2[idx];
            sw[KYW3o + idx] = 0.5f * kyW3[idx];
            sw[KGW3o + idx] = 0.5f * kgW3[idx];
        }
        if (tid < 4) { sw[KYB3o + tid] = 0.5f * kyb3[tid]; sw[KGB3o + tid] = 0.5f * kgb3[tid]; }
        if (tid < 32) sw[WOUTo + tid] = wout[tid];
    }
    __syncthreads();

    // ---- decode query (b, i, s) ----
    const int bid = blockIdx.x;
    const int b   = bid >> 9;
    const int rem = bid & 511;
    const int i   = rem >> 2;
    const int s   = rem & 3;

    float fq[CINc];
    {
        const float* fqp = f + (((size_t)b * Nc + i) * Sc + s) * CINc;
        float4 v = *reinterpret_cast<const float4*>(fqp);
        fq[0] = v.x; fq[1] = v.y; fq[2] = v.z; fq[3] = v.w;
    }

    // ---- two keys per thread: A=(j0,t), B=(j0+64,t) ----
    const int j0 = tid >> 2;
    const int t  = tid & 3;
    const int j1 = j0 + 64;

    // pointers (values reloaded per channel to keep registers free)
    const float* gpA = g + ((((((size_t)b * Nc + i) * Nc + j0) * Sc + s) * Sc) + t) * DGc;
    const float* gpB = gpA + (size_t)64 * Sc * Sc * DGc;
    const float* fkpA = f + (((size_t)b * Nc + j0) * Sc + t) * CINc;
    const float* fkpB = f + (((size_t)b * Nc + j1) * Sc + t) * CINc;

    const bool mkA = mask[((size_t)b * Nc + j0) * Sc + t] != 0;
    const bool mkB = mask[((size_t)b * Nc + j1) * Sc + t] != 0;

    float num[CINc], den[CINc];

    #pragma unroll 1
    for (int c = 0; c < CINc; ++c) {
        float kAt = 0.f, kBt = 0.f;
        u64 hpA[16], hpB[16];   // output-packed activations per position

        // per-channel key scalars (reloaded; address depends on c)
        float fkAc, fkBc;
        asm volatile("ld.global.nc.f32 %0, [%1];" : "=f"(fkAc) : "l"(fkpA + c));
        asm volatile("ld.global.nc.f32 %0, [%1];" : "=f"(fkBc) : "l"(fkpB + c));

        #pragma unroll 1
        for (int m = 0; m < 2; ++m) {
            // ===== layer 1 (output-packed, non-dup weights) =====
            if (m == 0) {
                const float* w1 = sw + KYW1t + c * 64;   // [k2][o]
                const float* b1 = sw + KYB1o + c * 32;
                const u64 fqd  = pk2(fq[c], fq[c]);
                const u64 fkAd = pk2(fkAc, fkAc);
                const u64 fkBd = pk2(fkBc, fkBc);
                #pragma unroll
                for (int q = 0; q < 8; ++q) {
                    ulonglong2 w0 = *reinterpret_cast<const ulonglong2*>(w1 + 4*q);       // k=0 (key)
                    ulonglong2 wq = *reinterpret_cast<const ulonglong2*>(w1 + 32 + 4*q);  // k=1 (query)
                    ulonglong2 bv = *reinterpret_cast<const ulonglong2*>(b1 + 4*q);
                    u64 t0 = fma2(fqd, wq.x, bv.x);
                    u64 t1 = fma2(fqd, wq.y, bv.y);
                    hpA[2*q]   = fma2(fkAd, w0.x, t0);
                    hpA[2*q+1] = fma2(fkAd, w0.y, t1);
                    hpB[2*q]   = fma2(fkBd, w0.x, t0);
                    hpB[2*q+1] = fma2(fkBd, w0.y, t1);
                }
            } else {
                // reload g per channel (volatile: keep out of persistent regs)
                float gA[DGc], gB[DGc];
                asm volatile("ld.global.nc.v4.f32 {%0,%1,%2,%3}, [%4];"
                             : "=f"(gA[0]), "=f"(gA[1]), "=f"(gA[2]), "=f"(gA[3]) : "l"(gpA));
                asm volatile("ld.global.nc.v4.f32 {%0,%1,%2,%3}, [%4];"
                             : "=f"(gA[4]), "=f"(gA[5]), "=f"(gA[6]), "=f"(gA[7]) : "l"(gpA + 4));
                asm volatile("ld.global.nc.v4.f32 {%0,%1,%2,%3}, [%4];"
                             : "=f"(gB[0]), "=f"(gB[1]), "=f"(gB[2]), "=f"(gB[3]) : "l"(gpB));
                asm volatile("ld.global.nc.v4.f32 {%0,%1,%2,%3}, [%4];"
                             : "=f"(gB[4]), "=f"(gB[5]), "=f"(gB[6]), "=f"(gB[7]) : "l"(gpB + 4));

                const float* w1 = sw + KGW1t + c * 256;   // [k8][o]
                const float* b1 = sw + KGB1o + c * 32;
                #pragma unroll
                for (int q = 0; q < 8; ++q) {
                    ulonglong2 bv = *reinterpret_cast<const ulonglong2*>(b1 + 4*q);
                    hpA[2*q] = bv.x; hpA[2*q+1] = bv.y;
                    hpB[2*q] = bv.x; hpB[2*q+1] = bv.y;
                }
                #pragma unroll
                for (int k = 0; k < DGc; ++k) {
                    const u64 gad = pk2(gA[k], gA[k]);
                    const u64 gbd = pk2(gB[k], gB[k]);
                    const float* wk = w1 + k * 32;
                    #pragma unroll
                    for (int q = 0; q < 8; ++q) {
                        ulonglong2 wv = *reinterpret_cast<const ulonglong2*>(wk + 4*q);
                        hpA[2*q]   = fma2(gad, wv.x, hpA[2*q]);
                        hpA[2*q+1] = fma2(gad, wv.y, hpA[2*q+1]);
                        hpB[2*q]   = fma2(gbd, wv.x, hpB[2*q]);
                        hpB[2*q+1] = fma2(gbd, wv.y, hpB[2*q+1]);
                    }
                }
            }
            // silu (pre-scaled form)
            #pragma unroll
            for (int p = 0; p < 16; ++p) {
                hpA[p] = silu2p(hpA[p]);
                hpB[p] = silu2p(hpB[p]);
            }

            // ===== fused layers 2+3 =====
            mlp23(hpA, hpB,
                  sw + (m ? KGW2t : KYW2t) + c * 1024,
                  sw + (m ? KGB2o : KYB2o) + c * HIDc,
                  sw + (m ? KGW3o : KYW3o) + c * HIDc,
                  sw[(m ? KGB3o : KYB3o) + c], kAt, kBt);
        }

        const float eA = mkA ? ex2f(LOG2E * kAt) : 0.0f;
        const float eB = mkB ? ex2f(LOG2E * kBt) : 0.0f;
        den[c] = eA + eB;
        num[c] = fmaf(eA, fkAc, eB * fkBc);
    }

    // ---- reduce over 256 threads (8 warps) ----
    #pragma unroll
    for (int c = 0; c < CINc; ++c) {
        #pragma unroll
        for (int off = 16; off > 0; off >>= 1) {
            num[c] += __shfl_xor_sync(0xFFFFFFFFu, num[c], off);
            den[c] += __shfl_xor_sync(0xFFFFFFFFu, den[c], off);
        }
    }
    const int wid = tid >> 5;
    const int lid = tid & 31;
    if (lid == 0) {
        #pragma unroll
        for (int c = 0; c < CINc; ++c) {
            sw[SREDo + wid * 8 + c]     = num[c];
            sw[SREDo + wid * 8 + 4 + c] = den[c];
        }
    }
    __syncthreads();

    if (tid < COUTc) {
        const int o = tid;
        const float mq = (mask[((size_t)b * Nc + i) * Sc + s] != 0) ? 1.0f : 0.0f;
        float acc = 0.0f;
        #pragma unroll
        for (int c = 0; c < CINc; ++c) {
            float n = 0.0f, d = 0.0f;
            #pragma unroll
            for (int w = 0; w < 8; ++w) {
                n += sw[SREDo + w * 8 + c];
                d += sw[SREDo + w * 8 + 4 + c];
            }
            const float cf = (fq[c] + n / d) * mq;
            acc = fmaf(cf, sw[WOUTo + o * CINc + c], acc);
        }
        out[(((size_t)b * Nc + i) * Sc + s) * COUTc + o] = acc;
    }
}

extern "C" void kernel_launch(void* const* d_in, const int* in_sizes, int n_in,
                              void* d_out, int out_size)
{
    const float* g    = (const float*)d_in[0];
    const float* f    = (const float*)d_in[1];
    const int*   mask = (const int*)d_in[2];
    const float* kyW1 = (const float*)d_in[3];
    const float* kyb1 = (const float*)d_in[4];
    const float* kyW2 = (const float*)d_in[5];
    const float* kyb2 = (const float*)d_in[6];
    const float* kyW3 = (const float*)d_in[7];
    const float* kyb3 = (const float*)d_in[8];
    const float* kgW1 = (const float*)d_in[9];
    const float* kgb1 = (const float*)d_in[10];
    const float* kgW2 = (const float*)d_in[11];
    const float* kgb2 = (const float*)d_in[12];
    const float* kgW3 = (const float*)d_in[13];
    const float* kgb3 = (const float*)d_in[14];
    const float* wout = (const float*)d_in[15];
    float* out = (float*)d_out;

    ema_kernel<<<Bc * Nc * Sc, 256>>>(g, f, mask,
                                      kyW1, kyb1, kyW2, kyb2, kyW3, kyb3,
                                      kgW1, kgb1, kgW2, kgb2, kgW3, kgb3,
                                      wout, out);
}

// round 10
// speedup vs baseline: 1.0008x; 1.0008x over previous
#include <cuda_runtime.h>
#include <cstdint>

// Problem constants
#define Bc    2
#define Nc    128
#define Sc    4
#define DGc   8
#define CINc  4
#define COUTc 8
#define HIDc  32

// Static smem layout (float offsets). ALL weights non-duplicated, input-major
// [c][k][o]; all weights & biases pre-scaled by 0.5 at staging (silu trick).
#define KYW1t 0        // [c][k2][o]   256
#define KGW1t 256      // [c][k8][o]   1024
#define KYB1o 1280     // [c][o]       128
#define KGB1o 1408     // 128
#define KYW2t 1536     // [c][k32][o]  4096
#define KGW2t 5632     // 4096
#define KYB2o 9728     // 128
#define KGB2o 9856     // 128
#define KYW3o 9984     // 128
#define KGW3o 10112    // 128
#define KYB3o 10240    // 4
#define KGB3o 10244    // 4
#define WOUTo 10248    // 32
#define SREDo 10280    // 64
#define SWTOT 10344

typedef unsigned long long u64;

__device__ __forceinline__ u64 pk2(float lo, float hi) {
    u64 r; asm("mov.b64 %0, {%1, %2};" : "=l"(r) : "f"(lo), "f"(hi)); return r;
}
__device__ __forceinline__ void upk2(u64 v, float& lo, float& hi) {
    asm("mov.b64 {%0, %1}, %2;" : "=f"(lo), "=f"(hi) : "l"(v));
}
__device__ __forceinline__ u64 fma2(u64 a, u64 b, u64 c) {
    u64 d; asm("fma.rn.f32x2 %0, %1, %2, %3;" : "=l"(d) : "l"(a), "l"(b), "l"(c)); return d;
}
__device__ __forceinline__ u64 add2(u64 a, u64 b) {
    u64 d; asm("add.rn.f32x2 %0, %1, %2;" : "=l"(d) : "l"(a), "l"(b)); return d;
}
__device__ __forceinline__ float ex2f(float x) {
    float r; asm("ex2.approx.f32 %0, %1;" : "=f"(r) : "f"(x)); return r;
}
__device__ __forceinline__ float tanhf_a(float x) {
    float r; asm("tanh.approx.f32 %0, %1;" : "=f"(r) : "f"(x)); return r;
}

#define LOG2E 1.4426950408889634f

// Pre-scaled silu: acc holds x/2; silu(x) = fma(acc, tanh(acc), acc).
__device__ __forceinline__ u64 silu2p(u64 acc) {
    float a, b; upk2(acc, a, b);
    u64 tp = pk2(tanhf_a(a), tanhf_a(b));
    return fma2(acc, tp, acc);
}
__device__ __forceinline__ float silu_fp(float acc) {
    return fmaf(acc, tanhf_a(acc), acc);
}

// Fused layers 2+3, 4 chunks of 8 outputs (small acc footprint).
__device__ __forceinline__ void mlp23(const u64* hpA, const u64* hpB,
                                      const float* __restrict__ w2,
                                      const float* __restrict__ b2,
                                      const float* __restrict__ w3,
                                      float b3, float& kA, float& kB)
{
    u64 tA = pk2(0.f, 0.f), tB = pk2(0.f, 0.f);

    #pragma unroll 1
    for (int ch = 0; ch < 4; ++ch) {
        u64 aA[4], aB[4];
        {
            ulonglong2 b01 = *reinterpret_cast<const ulonglong2*>(b2 + ch*8);
            ulonglong2 b23 = *reinterpret_cast<const ulonglong2*>(b2 + ch*8 + 4);
            aA[0]=b01.x; aA[1]=b01.y; aA[2]=b23.x; aA[3]=b23.y;
            aB[0]=b01.x; aB[1]=b01.y; aB[2]=b23.x; aB[3]=b23.y;
        }
        const float* wkb = w2 + ch*8;
        #pragma unroll
        for (int p = 0; p < 16; ++p) {
            float ha0, ha1, hb0, hb1;
            upk2(hpA[p], ha0, ha1);
            upk2(hpB[p], hb0, hb1);
            {   // k = 2p
                const u64 hAd = pk2(ha0, ha0);
                const u64 hBd = pk2(hb0, hb0);
                ulonglong2 w01 = *reinterpret_cast<const ulonglong2*>(wkb + (2*p)*32);
                ulonglong2 w23 = *reinterpret_cast<const ulonglong2*>(wkb + (2*p)*32 + 4);
                aA[0] = fma2(hAd, w01.x, aA[0]);
                aA[1] = fma2(hAd, w01.y, aA[1]);
                aA[2] = fma2(hAd, w23.x, aA[2]);
                aA[3] = fma2(hAd, w23.y, aA[3]);
                aB[0] = fma2(hBd, w01.x, aB[0]);
                aB[1] = fma2(hBd, w01.y, aB[1]);
                aB[2] = fma2(hBd, w23.x, aB[2]);
                aB[3] = fma2(hBd, w23.y, aB[3]);
            }
            {   // k = 2p+1
                const u64 hAd = pk2(ha1, ha1);
                const u64 hBd = pk2(hb1, hb1);
                ulonglong2 w01 = *reinterpret_cast<const ulonglong2*>(wkb + (2*p+1)*32);
                ulonglong2 w23 = *reinterpret_cast<const ulonglong2*>(wkb + (2*p+1)*32 + 4);
                aA[0] = fma2(hAd, w01.x, aA[0]);
                aA[1] = fma2(hAd, w01.y, aA[1]);
                aA[2] = fma2(hAd, w23.x, aA[2]);
                aA[3] = fma2(hAd, w23.y, aA[3]);
                aB[0] = fma2(hBd, w01.x, aB[0]);
                aB[1] = fma2(hBd, w01.y, aB[1]);
                aB[2] = fma2(hBd, w23.x, aB[2]);
                aB[3] = fma2(hBd, w23.y, aB[3]);
            }
        }
        // silu + fold into layer-3 dot (w3 pre-scaled)
        ulonglong2 p01 = *reinterpret_cast<const ulonglong2*>(w3 + ch*8);
        ulonglong2 p23 = *reinterpret_cast<const ulonglong2*>(w3 + ch*8 + 4);
        tA = fma2(silu2p(aA[0]), p01.x, tA);
        tB = fma2(silu2p(aB[0]), p01.x, tB);
        tA = fma2(silu2p(aA[1]), p01.y, tA);
        tB = fma2(silu2p(aB[1]), p01.y, tB);
        tA = fma2(silu2p(aA[2]), p23.x, tA);
        tB = fma2(silu2p(aB[2]), p23.x, tB);
        tA = fma2(silu2p(aA[3]), p23.y, tA);
        tB = fma2(silu2p(aB[3]), p23.y, tB);
    }
    float a0, a1, b0, b1v;
    upk2(tA, a0, a1);
    upk2(tB, b0, b1v);
    kA += silu_fp(a0 + a1 + b3);
    kB += silu_fp(b0 + b1v + b3);
}

__global__ __launch_bounds__(256, 2)
void ema_kernel(const float* __restrict__ g,
                const float* __restrict__ f,
                const int* __restrict__ mask,
                const float* __restrict__ kyW1, const float* __restrict__ kyb1,
                const float* __restrict__ kyW2, const float* __restrict__ kyb2,
                const float* __restrict__ kyW3, const float* __restrict__ kyb3,
                const float* __restrict__ kgW1, const float* __restrict__ kgb1,
                const float* __restrict__ kgW2, const float* __restrict__ kgb2,
                const float* __restrict__ kgW3, const float* __restrict__ kgb3,
                const float* __restrict__ wout,
                float* __restrict__ out)
{
    __shared__ __align__(16) float sw[SWTOT];

    const int tid = threadIdx.x;

    // ---- stage weights: transpose to input-major, pre-scale by 0.5 ----
    {
        for (int idx = tid; idx < 4096; idx += 256) {
            int c = idx >> 10, o = (idx >> 5) & 31, k = idx & 31;
            int d = c * 1024 + k * 32 + o;
            sw[KYW2t + d] = 0.5f * kyW2[idx];
            sw[KGW2t + d] = 0.5f * kgW2[idx];
        }
        for (int idx = tid; idx < 1024; idx += 256) {
            int c = idx >> 8, o = (idx >> 3) & 31, k = idx & 7;
            sw[KGW1t + c * 256 + k * 32 + o] = 0.5f * kgW1[idx];
        }
        if (tid < 256) {
            int idx = tid;
            int c = idx >> 6, o = (idx >> 1) & 31, k = idx & 1;
            sw[KYW1t + c * 64 + k * 32 + o] = 0.5f * kyW1[idx];
        }
        for (int idx = tid; idx < 128; idx += 256) {
            sw[KYB1o + idx] = 0.5f * kyb1[idx];
            sw[KGB1o + idx] = 0.5f * kgb1[idx];
            sw[KYB2o + idx] = 0.5f * kyb2[idx];
            sw[KGB2o + idx] = 0.5f * kgb2[idx];
            sw[KYW3o + idx] = 0.5f * kyW3[idx];
            sw[KGW3o + idx] = 0.5f * kgW3[idx];
        }
        if (tid < 4) { sw[KYB3o + tid] = 0.5f * kyb3[tid]; sw[KGB3o + tid] = 0.5f * kgb3[tid]; }
        if (tid < 32) sw[WOUTo + tid] = wout[tid];
    }
    __syncthreads();

    // ---- decode query (b, i, s) ----
    const int bid = blockIdx.x;
    const int b   = bid >> 9;
    const int rem = bid & 511;
    const int i   = rem >> 2;
    const int s   = rem & 3;

    float fq[CINc];
    {
        const float* fqp = f + (((size_t)b * Nc + i) * Sc + s) * CINc;
        float4 v = *reinterpret_cast<const float4*>(fqp);
        fq[0] = v.x; fq[1] = v.y; fq[2] = v.z; fq[3] = v.w;
    }

    // ---- two keys per thread: A=(j0,t), B=(j0+64,t) ----
    const int j0 = tid >> 2;
    const int t  = tid & 3;
    const int j1 = j0 + 64;

    // pointers (values reloaded per channel to keep registers free)
    const float* gpA = g + ((((((size_t)b * Nc + i) * Nc + j0) * Sc + s) * Sc) + t) * DGc;
    const float* gpB = gpA + (size_t)64 * Sc * Sc * DGc;
    const float* fkpA = f + (((size_t)b * Nc + j0) * Sc + t) * CINc;
    const float* fkpB = f + (((size_t)b * Nc + j1) * Sc + t) * CINc;

    const bool mkA = mask[((size_t)b * Nc + j0) * Sc + t] != 0;
    const bool mkB = mask[((size_t)b * Nc + j1) * Sc + t] != 0;

    float num[CINc], den[CINc];

    #pragma unroll 1
    for (int c = 0; c < CINc; ++c) {
        float kAt = 0.f, kBt = 0.f;
        u64 hpA[16], hpB[16];   // output-packed activations per position

        // per-channel key scalars (reloaded; address depends on c)
        float fkAc, fkBc;
        asm volatile("ld.global.nc.f32 %0, [%1];" : "=f"(fkAc) : "l"(fkpA + c));
        asm volatile("ld.global.nc.f32 %0, [%1];" : "=f"(fkBc) : "l"(fkpB + c));

        #pragma unroll 1
        for (int m = 0; m < 2; ++m) {
            // ===== layer 1 (output-packed, non-dup weights) =====
            if (m == 0) {
                const float* w1 = sw + KYW1t + c * 64;   // [k2][o]
                const float* b1 = sw + KYB1o + c * 32;
                const u64 fqd  = pk2(fq[c], fq[c]);
                const u64 fkAd = pk2(fkAc, fkAc);
                const u64 fkBd = pk2(fkBc, fkBc);
                #pragma unroll
                for (int q = 0; q < 8; ++q) {
                    ulonglong2 w0 = *reinterpret_cast<const ulonglong2*>(w1 + 4*q);       // k=0 (key)
                    ulonglong2 wq = *reinterpret_cast<const ulonglong2*>(w1 + 32 + 4*q);  // k=1 (query)
                    ulonglong2 bv = *reinterpret_cast<const ulonglong2*>(b1 + 4*q);
                    u64 t0 = fma2(fqd, wq.x, bv.x);
                    u64 t1 = fma2(fqd, wq.y, bv.y);
                    hpA[2*q]   = fma2(fkAd, w0.x, t0);
                    hpA[2*q+1] = fma2(fkAd, w0.y, t1);
                    hpB[2*q]   = fma2(fkBd, w0.x, t0);
                    hpB[2*q+1] = fma2(fkBd, w0.y, t1);
                }
            } else {
                // reload g per channel (volatile: keep out of persistent regs)
                float gA[DGc], gB[DGc];
                asm volatile("ld.global.nc.v4.f32 {%0,%1,%2,%3}, [%4];"
                             : "=f"(gA[0]), "=f"(gA[1]), "=f"(gA[2]), "=f"(gA[3]) : "l"(gpA));
                asm volatile("ld.global.nc.v4.f32 {%0,%1,%2,%3}, [%4];"
                             : "=f"(gA[4]), "=f"(gA[5]), "=f"(gA[6]), "=f"(gA[7]) : "l"(gpA + 4));
                asm volatile("ld.global.nc.v4.f32 {%0,%1,%2,%3}, [%4];"
                             : "=f"(gB[0]), "=f"(gB[1]), "=f"(gB[2]), "=f"(gB[3]) : "l"(gpB));
                asm volatile("ld.global.nc.v4.f32 {%0,%1,%2,%3}, [%4];"
                             : "=f"(gB[4]), "=f"(gB[5]), "=f"(gB[6]), "=f"(gB[7]) : "l"(gpB + 4));

                const float* w1 = sw + KGW1t + c * 256;   // [k8][o]
                const float* b1 = sw + KGB1o + c * 32;
                #pragma unroll
                for (int q = 0; q < 8; ++q) {
                    ulonglong2 bv = *reinterpret_cast<const ulonglong2*>(b1 + 4*q);
                    hpA[2*q] = bv.x; hpA[2*q+1] = bv.y;
                    hpB[2*q] = bv.x; hpB[2*q+1] = bv.y;
                }
                #pragma unroll
                for (int k = 0; k < DGc; ++k) {
                    const u64 gad = pk2(gA[k], gA[k]);
                    const u64 gbd = pk2(gB[k], gB[k]);
                    const float* wk = w1 + k * 32;
                    #pragma unroll
                    for (int q = 0; q < 8; ++q) {
                        ulonglong2 wv = *reinterpret_cast<const ulonglong2*>(wk + 4*q);
                        hpA[2*q]   = fma2(gad, wv.x, hpA[2*q]);
                        hpA[2*q+1] = fma2(gad, wv.y, hpA[2*q+1]);
                        hpB[2*q]   = fma2(gbd, wv.x, hpB[2*q]);
                        hpB[2*q+1] = fma2(gbd, wv.y, hpB[2*q+1]);
                    }
                }
            }
            // silu (pre-scaled form)
            #pragma unroll
            for (int p = 0; p < 16; ++p) {
                hpA[p] = silu2p(hpA[p]);
                hpB[p] = silu2p(hpB[p]);
            }

            // ===== fused layers 2+3 =====
            mlp23(hpA, hpB,
                  sw + (m ? KGW2t : KYW2t) + c * 1024,
                  sw + (m ? KGB2o : KYB2o) + c * HIDc,
                  sw + (m ? KGW3o : KYW3o) + c * HIDc,
                  sw[(m ? KGB3o : KYB3o) + c], kAt, kBt);
        }

        const float eA = mkA ? ex2f(LOG2E * kAt) : 0.0f;
        const float eB = mkB ? ex2f(LOG2E * kBt) : 0.0f;
        den[c] = eA + eB;
        num[c] = fmaf(eA, fkAc, eB * fkBc);
    }

    // ---- reduce over 256 threads (8 warps) ----
    #pragma unroll
    for (int c = 0; c < CINc; ++c) {
        #pragma unroll
        for (int off = 16; off > 0; off >>= 1) {
            num[c] += __shfl_xor_sync(0xFFFFFFFFu, num[c], off);
            den[c] += __shfl_xor_sync(0xFFFFFFFFu, den[c], off);
        }
    }
    const int wid = tid >> 5;
    const int lid = tid & 31;
    if (lid == 0) {
        #pragma unroll
        for (int c = 0; c < CINc; ++c) {
            sw[SREDo + wid * 8 + c]     = num[c];
            sw[SREDo + wid * 8 + 4 + c] = den[c];
        }
    }
    __syncthreads();

    if (tid < COUTc) {
        const int o = tid;
        const float mq = (mask[((size_t)b * Nc + i) * Sc + s] != 0) ? 1.0f : 0.0f;
        float acc = 0.0f;
        #pragma unroll
        for (int c = 0; c < CINc; ++c) {
            float n = 0.0f, d = 0.0f;
            #pragma unroll
            for (int w = 0; w < 8; ++w) {
                n += sw[SREDo + w * 8 + c];
                d += sw[SREDo + w * 8 + 4 + c];
            }
            const float cf = (fq[c] + n / d) * mq;
            acc = fmaf(cf, sw[WOUTo + o * CINc + c], acc);
        }
        out[(((size_t)b * Nc + i) * Sc + s) * COUTc + o] = acc;
    }
}

extern "C" void kernel_launch(void* const* d_in, const int* in_sizes, int n_in,
                              void* d_out, int out_size)
{
    const float* g    = (const float*)d_in[0];
    const float* f    = (const float*)d_in[1];
    const int*   mask = (const int*)d_in[2];
    const float* kyW1 = (const float*)d_in[3];
    const float* kyb1 = (const float*)d_in[4];
    const float* kyW2 = (const float*)d_in[5];
    const float* kyb2 = (const float*)d_in[6];
    const float* kyW3 = (const float*)d_in[7];
    const float* kyb3 = (const float*)d_in[8];
    const float* kgW1 = (const float*)d_in[9];
    const float* kgb1 = (const float*)d_in[10];
    const float* kgW2 = (const float*)d_in[11];
    const float* kgb2 = (const float*)d_in[12];
    const float* kgW3 = (const float*)d_in[13];
    const float* kgb3 = (const float*)d_in[14];
    const float* wout = (const float*)d_in[15];
    float* out = (float*)d_out;

    ema_kernel<<<Bc * Nc * Sc, 256>>>(g, f, mask,
                                      kyW1, kyb1, kyW2, kyb2, kyW3, kyb3,
                                      kgW1, kgb1, kgW2, kgb2, kgW3, kgb3,
                                      wout, out);
}